// round 1
// baseline (speedup 1.0000x reference)
#include <cuda_runtime.h>
#include <cuda_bf16.h>
#include <math.h>

#define HIDDEN 128
#define NPTS   4096            // interpolation intervals over s in [0, 10]
#define TAB_N  (NPTS + 4)      // +1 guard point below, +2 above (Catmull-Rom)
#define S_MAX  10.0f           // 1/sqrt(EPS2)
#define EPS2   0.01f
#define BLK    256

// Scratch: derivative table g(s) = dMLP/ds at s_k = (k-1)*h, k = 0..NPTS+3
__device__ float g_table[TAB_N];

// ---------------------------------------------------------------------------
// Kernel 1: build the 1-D derivative table. One point per warp.
// W2 staged in shared memory padded to row stride 129 floats -> bank-conflict
// free for BOTH row access (forward, lane stride 129) and column access
// (backward, lane stride 1).
// ---------------------------------------------------------------------------
__global__ void build_table_kernel(const float* __restrict__ W1,
                                   const float* __restrict__ b1,
                                   const float* __restrict__ W2,
                                   const float* __restrict__ b2,
                                   const float* __restrict__ W3)
{
    extern __shared__ float sm[];
    float* sW2  = sm;                       // [128][129]
    float* sbuf = sm + 128 * 129;           // per-warp: 128 h1 + 128 g2

    // Stage W2 (64 KB) with padding
    for (int idx = threadIdx.x; idx < 128 * 128; idx += blockDim.x) {
        sW2[(idx >> 7) * 129 + (idx & 127)] = W2[idx];
    }
    __syncthreads();

    const int warp = threadIdx.x >> 5;
    const int lane = threadIdx.x & 31;
    float* sh1 = sbuf + warp * 256;
    float* sg2 = sh1 + 128;

    const int nwarps = (blockDim.x >> 5) * gridDim.x;
    const int gw     = blockIdx.x * (blockDim.x >> 5) + warp;
    const float hstep = S_MAX / (float)NPTS;

    for (int pt = gw; pt < TAB_N; pt += nwarps) {
        const float s = (float)(pt - 1) * hstep;

        // ---- layer 1: a1 = W1*s + b1, h1 = silu(a1); keep silu'(a1) ----
        float sp1[4];
        #pragma unroll
        for (int m = 0; m < 4; m++) {
            const int j = lane + 32 * m;
            const float a  = fmaf(W1[j], s, b1[j]);
            const float sg = 1.0f / (1.0f + __expf(-a));
            sh1[j] = a * sg;                         // silu
            sp1[m] = sg * (1.0f + a * (1.0f - sg));  // silu'
        }
        __syncwarp();

        // ---- layer 2 forward: a2 = W2 @ h1 + b2; g2 = W3 * silu'(a2) ----
        {
            float acc0 = b2[lane];
            float acc1 = b2[lane + 32];
            float acc2 = b2[lane + 64];
            float acc3 = b2[lane + 96];
            const float* w0 = sW2 + lane * 129;
            #pragma unroll 4
            for (int j = 0; j < 128; j++) {
                const float hj = sh1[j];
                acc0 = fmaf(w0[j],             hj, acc0);
                acc1 = fmaf(w0[32 * 129 + j],  hj, acc1);
                acc2 = fmaf(w0[64 * 129 + j],  hj, acc2);
                acc3 = fmaf(w0[96 * 129 + j],  hj, acc3);
            }
            #pragma unroll
            for (int m = 0; m < 4; m++) {
                const float a  = (m == 0) ? acc0 : (m == 1) ? acc1 : (m == 2) ? acc2 : acc3;
                const int   r  = lane + 32 * m;
                const float sg = 1.0f / (1.0f + __expf(-a));
                sg2[r] = W3[r] * sg * (1.0f + a * (1.0f - sg));
            }
        }
        __syncwarp();

        // ---- backward: gh1 = W2^T @ g2; f'(s) = sum_j W1[j]*silu'(a1_j)*gh1_j
        float tot;
        {
            float a0 = 0.f, a1 = 0.f, a2 = 0.f, a3 = 0.f;
            #pragma unroll 4
            for (int k = 0; k < 128; k++) {
                const float gk = sg2[k];
                const float* wr = sW2 + k * 129 + lane;
                a0 = fmaf(wr[0],  gk, a0);
                a1 = fmaf(wr[32], gk, a1);
                a2 = fmaf(wr[64], gk, a2);
                a3 = fmaf(wr[96], gk, a3);
            }
            tot = W1[lane]      * sp1[0] * a0
                + W1[lane + 32] * sp1[1] * a1
                + W1[lane + 64] * sp1[2] * a2
                + W1[lane + 96] * sp1[3] * a3;
        }
        #pragma unroll
        for (int off = 16; off; off >>= 1)
            tot += __shfl_xor_sync(0xffffffffu, tot, off);
        if (lane == 0) g_table[pt] = tot;
        __syncwarp();
    }
}

// Catmull-Rom lookup of g(s); s in (0, S_MAX] (slight over-range is clamped)
__device__ __forceinline__ float lookup_g(float s)
{
    const float inv_h = (float)NPTS / S_MAX;
    float u = s * inv_h;
    int i = (int)u;                       // s > 0 -> trunc == floor
    if (i > NPTS - 1) i = NPTS - 1;
    const float t  = u - (float)i;
    const float p0 = g_table[i];
    const float p1 = g_table[i + 1];
    const float p2 = g_table[i + 2];
    const float p3 = g_table[i + 3];
    return p1 + 0.5f * t * ((p2 - p0)
           + t * ((2.0f * p0 - 5.0f * p1 + 4.0f * p2 - p3)
           + t * (3.0f * (p1 - p2) + (p3 - p0))));
}

// ---------------------------------------------------------------------------
// Kernel 2: one thread per sample. Smem-staged I/O for coalescing (rows are
// 72 B; raw per-thread loads would shatter across ~19 lines per instruction).
// ---------------------------------------------------------------------------
__global__ void hnn_kernel(const float* __restrict__ z,
                           const float* __restrict__ log_m,
                           float* __restrict__ out, int B)
{
    __shared__ float sz[BLK][19];   // stride 19 -> conflict-free row reads

    const int row0  = blockIdx.x * BLK;
    const int nrows = min(BLK, B - row0);
    const int nelem = nrows * 18;
    const long long base = (long long)row0 * 18;

    for (int idx = threadIdx.x; idx < nelem; idx += BLK) {
        sz[idx / 18][idx % 18] = z[base + idx];
    }
    __syncthreads();

    float dq[9], f[9];
    const int t = threadIdx.x;
    if (t < nrows) {
        float q[9], p[9];
        #pragma unroll
        for (int c = 0; c < 9; c++) { q[c] = sz[t][c]; p[c] = sz[t][9 + c]; }

        const float mi0 = 1.0f / (expf(log_m[0]) + 1e-8f);
        const float mi1 = 1.0f / (expf(log_m[1]) + 1e-8f);
        const float mi2 = 1.0f / (expf(log_m[2]) + 1e-8f);

        #pragma unroll
        for (int c = 0; c < 3; c++) {
            dq[c]     = p[c]     * mi0;
            dq[3 + c] = p[3 + c] * mi1;
            dq[6 + c] = p[6 + c] * mi2;
        }
        #pragma unroll
        for (int c = 0; c < 9; c++) f[c] = 0.0f;

        const int PI[3] = {0, 0, 1};
        const int PJ[3] = {1, 2, 2};
        #pragma unroll
        for (int pr = 0; pr < 3; pr++) {
            const int bi = PI[pr] * 3, bj = PJ[pr] * 3;
            const float dx = q[bi]     - q[bj];
            const float dy = q[bi + 1] - q[bj + 1];
            const float dz = q[bi + 2] - q[bj + 2];
            const float r2 = fmaf(dx, dx, fmaf(dy, dy, fmaf(dz, dz, EPS2)));
            const float s  = rsqrtf(r2);          // s = 1/d
            const float g  = lookup_g(s);         // dV_pair/ds
            const float w  = g * s * s * s;       // g / d^3
            // dpdt = -dV/dq: body i gets +w*diff, body j gets -w*diff
            f[bi]     += w * dx;  f[bi + 1] += w * dy;  f[bi + 2] += w * dz;
            f[bj]     -= w * dx;  f[bj + 1] -= w * dy;  f[bj + 2] -= w * dz;
        }
    }
    __syncthreads();   // before reusing sz as output staging

    if (t < nrows) {
        #pragma unroll
        for (int c = 0; c < 9; c++) {
            sz[t][c]     = dq[c];   // dq/dt = dH/dp
            sz[t][9 + c] = f[c];    // dp/dt = -dH/dq
        }
    }
    __syncthreads();

    for (int idx = threadIdx.x; idx < nelem; idx += BLK) {
        out[base + idx] = sz[idx / 18][idx % 18];
    }
}

extern "C" void kernel_launch(void* const* d_in, const int* in_sizes, int n_in,
                              void* d_out, int out_size)
{
    const float* z     = (const float*)d_in[0];
    const float* log_m = (const float*)d_in[1];
    const float* W1    = (const float*)d_in[2];
    const float* b1    = (const float*)d_in[3];
    const float* W2    = (const float*)d_in[4];
    const float* b2    = (const float*)d_in[5];
    const float* W3    = (const float*)d_in[6];
    // d_in[7] = b3: constant offset, drops out of the gradient
    float* out = (float*)d_out;
    const int B = in_sizes[0] / 18;

    const size_t smem = (128 * 129 + 8 * 256) * sizeof(float);  // 74240 B
    cudaFuncSetAttribute(build_table_kernel,
                         cudaFuncAttributeMaxDynamicSharedMemorySize, (int)smem);

    build_table_kernel<<<148, 256, smem>>>(W1, b1, W2, b2, W3);
    hnn_kernel<<<(B + BLK - 1) / BLK, BLK>>>(z, log_m, out, B);
}

// round 3
// speedup vs baseline: 2.0377x; 2.0377x over previous
#include <cuda_runtime.h>
#include <cuda_bf16.h>
#include <math.h>

#define NPTS   1024            // interpolation intervals over s in [0, 10]
#define TAB_N  (NPTS + 4)      // +1 guard point below, +2 above (Catmull-Rom)
#define S_MAX  10.0f           // 1/sqrt(EPS2)
#define EPS2   0.01f
#define BLK    256
#define SPB    512             // samples per block in hnn_kernel

// g(s) = d(MLP)/ds at s_k = (k-1)*h, k = 0..NPTS+3
__device__ float g_table[TAB_N];
__device__ float minv_g[3];

// ---------------------------------------------------------------------------
// Kernel 1: build the 1-D derivative table. One point per warp.
// Fused forward+backward: tot = sum_k g2_k * (W2 @ u)_k with u_j = W1_j*silu'(a1_j),
// so W2 is traversed ONCE, row-major, with two accumulators per output row.
// W2 staged in smem padded to stride 129 -> conflict-free row access.
// ---------------------------------------------------------------------------
__global__ void build_table_kernel(const float* __restrict__ W1,
                                   const float* __restrict__ b1,
                                   const float* __restrict__ W2,
                                   const float* __restrict__ b2,
                                   const float* __restrict__ W3,
                                   const float* __restrict__ log_m)
{
    extern __shared__ float sm[];
    float* sW2  = sm;                       // [128][129]
    float* sbuf = sm + 128 * 129;           // per-warp: 128 h1 + 128 u

    // Stage W2 via float4 loads, scalar padded stores
    const float4* W24 = (const float4*)W2;
    for (int idx = threadIdx.x; idx < 128 * 32; idx += blockDim.x) {
        const float4 v = W24[idx];
        float* d = sW2 + (idx >> 5) * 129 + ((idx & 31) << 2);
        d[0] = v.x; d[1] = v.y; d[2] = v.z; d[3] = v.w;
    }
    if (blockIdx.x == 0 && threadIdx.x < 3)
        minv_g[threadIdx.x] = 1.0f / (expf(log_m[threadIdx.x]) + 1e-8f);
    __syncthreads();

    const int warp = threadIdx.x >> 5;
    const int lane = threadIdx.x & 31;
    float* sh1 = sbuf + warp * 256;
    float* su  = sh1 + 128;

    const int nwarps = (blockDim.x >> 5) * gridDim.x;
    const int gw     = blockIdx.x * (blockDim.x >> 5) + warp;
    const float hstep = S_MAX / (float)NPTS;

    for (int pt = gw; pt < TAB_N; pt += nwarps) {
        const float s = (float)(pt - 1) * hstep;

        // layer 1: h1 = silu(a1), u = W1 * silu'(a1)
        #pragma unroll
        for (int m = 0; m < 4; m++) {
            const int j = lane + 32 * m;
            const float w  = W1[j];
            const float a  = fmaf(w, s, b1[j]);
            const float sg = 1.0f / (1.0f + __expf(-a));
            sh1[j] = a * sg;
            su[j]  = w * sg * (1.0f + a * (1.0f - sg));
        }
        __syncwarp();

        // one pass over W2: acch = W2@h1 + b2 (rows), accu = W2@u (rows)
        float acch0 = b2[lane], acch1 = b2[lane + 32],
              acch2 = b2[lane + 64], acch3 = b2[lane + 96];
        float accu0 = 0.f, accu1 = 0.f, accu2 = 0.f, accu3 = 0.f;
        const float* w0 = sW2 + lane * 129;
        #pragma unroll 4
        for (int j = 0; j < 128; j++) {
            const float hj = sh1[j];
            const float uj = su[j];
            const float wa = w0[j];
            const float wb = w0[32 * 129 + j];
            const float wc = w0[64 * 129 + j];
            const float wd = w0[96 * 129 + j];
            acch0 = fmaf(wa, hj, acch0);  accu0 = fmaf(wa, uj, accu0);
            acch1 = fmaf(wb, hj, acch1);  accu1 = fmaf(wb, uj, accu1);
            acch2 = fmaf(wc, hj, acch2);  accu2 = fmaf(wc, uj, accu2);
            acch3 = fmaf(wd, hj, acch3);  accu3 = fmaf(wd, uj, accu3);
        }

        // tot = sum_k W3_k * silu'(a2_k) * accu_k
        float tot = 0.0f;
        #pragma unroll
        for (int m = 0; m < 4; m++) {
            const float a  = (m == 0) ? acch0 : (m == 1) ? acch1 : (m == 2) ? acch2 : acch3;
            const float au = (m == 0) ? accu0 : (m == 1) ? accu1 : (m == 2) ? accu2 : accu3;
            const float sg = 1.0f / (1.0f + __expf(-a));
            tot = fmaf(W3[lane + 32 * m] * sg * (1.0f + a * (1.0f - sg)), au, tot);
        }
        #pragma unroll
        for (int off = 16; off; off >>= 1)
            tot += __shfl_xor_sync(0xffffffffu, tot, off);
        if (lane == 0) g_table[pt] = tot;
        __syncwarp();   // protect sh1/su before next iteration
    }
}

// Catmull-Rom lookup of g(s) from a shared-memory table
__device__ __forceinline__ float lookup_g(const float* __restrict__ tab, float s)
{
    const float inv_h = (float)NPTS / S_MAX;
    const float u = s * inv_h;
    int i = (int)u;
    if (i > NPTS - 1) i = NPTS - 1;
    const float t  = u - (float)i;
    const float p0 = tab[i];
    const float p1 = tab[i + 1];
    const float p2 = tab[i + 2];
    const float p3 = tab[i + 3];
    return p1 + 0.5f * t * ((p2 - p0)
           + t * ((2.0f * p0 - 5.0f * p1 + 4.0f * p2 - p3)
           + t * (3.0f * (p1 - p2) + (p3 - p0))));
}

// ---------------------------------------------------------------------------
// Kernel 2: 512 samples per 256-thread block. float4-coalesced smem staging
// (sz declared FIRST and 16B-aligned -> float4 casts are legal),
// table + mass inverses in smem.
// ---------------------------------------------------------------------------
__global__ void __launch_bounds__(BLK) hnn_kernel(const float* __restrict__ z,
                                                  float* __restrict__ out, int B)
{
    __shared__ __align__(16) float sz[SPB * 18];   // 36864 B, offset 0
    __shared__ __align__(16) float s_tab[TAB_N];
    __shared__ float s_minv[3];

    const int tid = threadIdx.x;
    for (int i = tid; i < TAB_N; i += BLK) s_tab[i] = g_table[i];
    if (tid < 3) s_minv[tid] = minv_g[tid];

    const int row0  = blockIdx.x * SPB;
    const int nrows = min(SPB, B - row0);
    const int nelem = nrows * 18;
    const long long base = (long long)row0 * 18;
    const int n4 = nelem >> 2;

    const float4* z4 = (const float4*)(z + base);
    float4* s4 = (float4*)sz;
    for (int i = tid; i < n4; i += BLK) s4[i] = z4[i];
    for (int i = (n4 << 2) + tid; i < nelem; i += BLK) sz[i] = z[base + i];
    __syncthreads();

    const float mi0 = s_minv[0], mi1 = s_minv[1], mi2 = s_minv[2];

    for (int t = tid; t < nrows; t += BLK) {
        float* r = sz + t * 18;
        float q[9], p[9], f[9];
        #pragma unroll
        for (int c = 0; c < 9; c++) { q[c] = r[c]; p[c] = r[9 + c]; }

        #pragma unroll
        for (int c = 0; c < 3; c++) {
            r[c]     = p[c]     * mi0;      // dq/dt
            r[3 + c] = p[3 + c] * mi1;
            r[6 + c] = p[6 + c] * mi2;
        }
        #pragma unroll
        for (int c = 0; c < 9; c++) f[c] = 0.0f;

        const int PI[3] = {0, 0, 1};
        const int PJ[3] = {1, 2, 2};
        #pragma unroll
        for (int pr = 0; pr < 3; pr++) {
            const int bi = PI[pr] * 3, bj = PJ[pr] * 3;
            const float dx = q[bi]     - q[bj];
            const float dy = q[bi + 1] - q[bj + 1];
            const float dz = q[bi + 2] - q[bj + 2];
            const float r2 = fmaf(dx, dx, fmaf(dy, dy, fmaf(dz, dz, EPS2)));
            const float s  = rsqrtf(r2);               // 1/d
            const float g  = lookup_g(s_tab, s);       // dV_pair/ds
            const float w  = g * s * s * s;            // g / d^3
            f[bi]     += w * dx;  f[bi + 1] += w * dy;  f[bi + 2] += w * dz;
            f[bj]     -= w * dx;  f[bj + 1] -= w * dy;  f[bj + 2] -= w * dz;
        }
        #pragma unroll
        for (int c = 0; c < 9; c++) r[9 + c] = f[c];   // dp/dt
    }
    __syncthreads();

    float4* o4 = (float4*)(out + base);
    for (int i = tid; i < n4; i += BLK) o4[i] = s4[i];
    for (int i = (n4 << 2) + tid; i < nelem; i += BLK) out[base + i] = sz[i];
}

extern "C" void kernel_launch(void* const* d_in, const int* in_sizes, int n_in,
                              void* d_out, int out_size)
{
    const float* z     = (const float*)d_in[0];
    const float* log_m = (const float*)d_in[1];
    const float* W1    = (const float*)d_in[2];
    const float* b1    = (const float*)d_in[3];
    const float* W2    = (const float*)d_in[4];
    const float* b2    = (const float*)d_in[5];
    const float* W3    = (const float*)d_in[6];
    // d_in[7] = b3 drops out of the gradient
    float* out = (float*)d_out;
    const int B = in_sizes[0] / 18;

    const size_t smem = (128 * 129 + 8 * 256) * sizeof(float);  // 74240 B
    cudaFuncSetAttribute(build_table_kernel,
                         cudaFuncAttributeMaxDynamicSharedMemorySize, (int)smem);

    // 129 blocks x 8 warps = 1032 warps >= 1028 table points (one point each)
    build_table_kernel<<<129, 256, smem>>>(W1, b1, W2, b2, W3, log_m);
    hnn_kernel<<<(B + SPB - 1) / SPB, BLK>>>(z, out, B);
}

// round 4
// speedup vs baseline: 2.1075x; 1.0343x over previous
#include <cuda_runtime.h>
#include <cuda_bf16.h>
#include <math.h>

#define NPTS   512             // interpolation intervals over s in [0, 10]
#define TAB_N  (NPTS + 4)      // +1 guard point below, +2 above (Catmull-Rom)
#define S_MAX  10.0f           // 1/sqrt(EPS2)
#define EPS2   0.01f
#define BLK    128
#define SPB    128             // samples per block in hnn_kernel

// g(s) = d(MLP)/ds at s_k = (k-1)*h, k = 0..NPTS+3
__device__ float g_table[TAB_N];
__device__ float minv_g[3];

// ---------------------------------------------------------------------------
// Kernel 1: build the 1-D derivative table. One point per warp.
// Fused forward+backward: tot = sum_k g2_k * (W2 @ u)_k with u_j = W1_j*silu'(a1_j),
// so W2 is traversed ONCE, row-major, with two accumulators per output row.
// W2 staged in smem padded to stride 129 -> conflict-free row access.
// ---------------------------------------------------------------------------
__global__ void build_table_kernel(const float* __restrict__ W1,
                                   const float* __restrict__ b1,
                                   const float* __restrict__ W2,
                                   const float* __restrict__ b2,
                                   const float* __restrict__ W3,
                                   const float* __restrict__ log_m)
{
    extern __shared__ float sm[];
    float* sW2  = sm;                       // [128][129]
    float* sbuf = sm + 128 * 129;           // per-warp: 128 h1 + 128 u

    // Stage W2 via float4 loads, scalar padded stores
    const float4* W24 = (const float4*)W2;
    for (int idx = threadIdx.x; idx < 128 * 32; idx += blockDim.x) {
        const float4 v = W24[idx];
        float* d = sW2 + (idx >> 5) * 129 + ((idx & 31) << 2);
        d[0] = v.x; d[1] = v.y; d[2] = v.z; d[3] = v.w;
    }
    if (blockIdx.x == 0 && threadIdx.x < 3)
        minv_g[threadIdx.x] = 1.0f / (expf(log_m[threadIdx.x]) + 1e-8f);
    __syncthreads();

    const int warp = threadIdx.x >> 5;
    const int lane = threadIdx.x & 31;
    float* sh1 = sbuf + warp * 256;
    float* su  = sh1 + 128;

    const int nwarps = (blockDim.x >> 5) * gridDim.x;
    const int gw     = blockIdx.x * (blockDim.x >> 5) + warp;
    const float hstep = S_MAX / (float)NPTS;

    for (int pt = gw; pt < TAB_N; pt += nwarps) {
        const float s = (float)(pt - 1) * hstep;

        // layer 1: h1 = silu(a1), u = W1 * silu'(a1)
        #pragma unroll
        for (int m = 0; m < 4; m++) {
            const int j = lane + 32 * m;
            const float w  = W1[j];
            const float a  = fmaf(w, s, b1[j]);
            const float sg = 1.0f / (1.0f + __expf(-a));
            sh1[j] = a * sg;
            su[j]  = w * sg * (1.0f + a * (1.0f - sg));
        }
        __syncwarp();

        // one pass over W2: acch = W2@h1 + b2 (rows), accu = W2@u (rows)
        float acch0 = b2[lane], acch1 = b2[lane + 32],
              acch2 = b2[lane + 64], acch3 = b2[lane + 96];
        float accu0 = 0.f, accu1 = 0.f, accu2 = 0.f, accu3 = 0.f;
        const float* w0 = sW2 + lane * 129;
        #pragma unroll 4
        for (int j = 0; j < 128; j++) {
            const float hj = sh1[j];
            const float uj = su[j];
            const float wa = w0[j];
            const float wb = w0[32 * 129 + j];
            const float wc = w0[64 * 129 + j];
            const float wd = w0[96 * 129 + j];
            acch0 = fmaf(wa, hj, acch0);  accu0 = fmaf(wa, uj, accu0);
            acch1 = fmaf(wb, hj, acch1);  accu1 = fmaf(wb, uj, accu1);
            acch2 = fmaf(wc, hj, acch2);  accu2 = fmaf(wc, uj, accu2);
            acch3 = fmaf(wd, hj, acch3);  accu3 = fmaf(wd, uj, accu3);
        }

        // tot = sum_k W3_k * silu'(a2_k) * accu_k
        float tot = 0.0f;
        #pragma unroll
        for (int m = 0; m < 4; m++) {
            const float a  = (m == 0) ? acch0 : (m == 1) ? acch1 : (m == 2) ? acch2 : acch3;
            const float au = (m == 0) ? accu0 : (m == 1) ? accu1 : (m == 2) ? accu2 : accu3;
            const float sg = 1.0f / (1.0f + __expf(-a));
            tot = fmaf(W3[lane + 32 * m] * sg * (1.0f + a * (1.0f - sg)), au, tot);
        }
        #pragma unroll
        for (int off = 16; off; off >>= 1)
            tot += __shfl_xor_sync(0xffffffffu, tot, off);
        if (lane == 0) g_table[pt] = tot;
        __syncwarp();   // protect sh1/su before next iteration
    }
}

// Catmull-Rom lookup of g(s) from a shared-memory table
__device__ __forceinline__ float lookup_g(const float* __restrict__ tab, float s)
{
    const float inv_h = (float)NPTS / S_MAX;
    const float u = s * inv_h;
    int i = (int)u;
    if (i > NPTS - 1) i = NPTS - 1;
    const float t  = u - (float)i;
    const float p0 = tab[i];
    const float p1 = tab[i + 1];
    const float p2 = tab[i + 2];
    const float p3 = tab[i + 3];
    return p1 + 0.5f * t * ((p2 - p0)
           + t * ((2.0f * p0 - 5.0f * p1 + 4.0f * p2 - p3)
           + t * (3.0f * (p1 - p2) + (p3 - p0))));
}

// ---------------------------------------------------------------------------
// Kernel 2: one sample per thread, 128-thread blocks -> grid 2048 so the SM
// occupancy is regfile-limited (~10 blocks/SM), not grid-limited, and the
// load/compute/store barrier phases overlap across many resident blocks.
// ---------------------------------------------------------------------------
__global__ void __launch_bounds__(BLK) hnn_kernel(const float* __restrict__ z,
                                                  float* __restrict__ out, int B)
{
    __shared__ __align__(16) float sz[SPB * 18];   // 9216 B, offset 0
    __shared__ __align__(16) float s_tab[TAB_N];
    __shared__ float s_minv[3];

    const int tid = threadIdx.x;
    for (int i = tid; i < TAB_N; i += BLK) s_tab[i] = g_table[i];
    if (tid < 3) s_minv[tid] = minv_g[tid];

    const int row0  = blockIdx.x * SPB;
    const int nrows = min(SPB, B - row0);
    const int nelem = nrows * 18;
    const long long base = (long long)row0 * 18;
    const int n4 = nelem >> 2;

    const float4* z4 = (const float4*)(z + base);
    float4* s4 = (float4*)sz;
    for (int i = tid; i < n4; i += BLK) s4[i] = z4[i];
    for (int i = (n4 << 2) + tid; i < nelem; i += BLK) sz[i] = z[base + i];
    __syncthreads();

    const float mi0 = s_minv[0], mi1 = s_minv[1], mi2 = s_minv[2];

    for (int t = tid; t < nrows; t += BLK) {
        float* r = sz + t * 18;
        float q[9], p[9], f[9];
        #pragma unroll
        for (int c = 0; c < 9; c++) { q[c] = r[c]; p[c] = r[9 + c]; }

        #pragma unroll
        for (int c = 0; c < 3; c++) {
            r[c]     = p[c]     * mi0;      // dq/dt
            r[3 + c] = p[3 + c] * mi1;
            r[6 + c] = p[6 + c] * mi2;
        }
        #pragma unroll
        for (int c = 0; c < 9; c++) f[c] = 0.0f;

        const int PI[3] = {0, 0, 1};
        const int PJ[3] = {1, 2, 2};
        #pragma unroll
        for (int pr = 0; pr < 3; pr++) {
            const int bi = PI[pr] * 3, bj = PJ[pr] * 3;
            const float dx = q[bi]     - q[bj];
            const float dy = q[bi + 1] - q[bj + 1];
            const float dz = q[bi + 2] - q[bj + 2];
            const float r2 = fmaf(dx, dx, fmaf(dy, dy, fmaf(dz, dz, EPS2)));
            const float s  = rsqrtf(r2);               // 1/d
            const float g  = lookup_g(s_tab, s);       // dV_pair/ds
            const float w  = g * s * s * s;            // g / d^3
            f[bi]     += w * dx;  f[bi + 1] += w * dy;  f[bi + 2] += w * dz;
            f[bj]     -= w * dx;  f[bj + 1] -= w * dy;  f[bj + 2] -= w * dz;
        }
        #pragma unroll
        for (int c = 0; c < 9; c++) r[9 + c] = f[c];   // dp/dt
    }
    __syncthreads();

    float4* o4 = (float4*)(out + base);
    for (int i = tid; i < n4; i += BLK) o4[i] = s4[i];
    for (int i = (n4 << 2) + tid; i < nelem; i += BLK) out[base + i] = sz[i];
}

extern "C" void kernel_launch(void* const* d_in, const int* in_sizes, int n_in,
                              void* d_out, int out_size)
{
    const float* z     = (const float*)d_in[0];
    const float* log_m = (const float*)d_in[1];
    const float* W1    = (const float*)d_in[2];
    const float* b1    = (const float*)d_in[3];
    const float* W2    = (const float*)d_in[4];
    const float* b2    = (const float*)d_in[5];
    const float* W3    = (const float*)d_in[6];
    // d_in[7] = b3 drops out of the gradient
    float* out = (float*)d_out;
    const int B = in_sizes[0] / 18;

    const size_t smem = (128 * 129 + 8 * 256) * sizeof(float);  // 74240 B
    cudaFuncSetAttribute(build_table_kernel,
                         cudaFuncAttributeMaxDynamicSharedMemorySize, (int)smem);

    // 65 blocks x 8 warps = 520 warps >= 516 table points (one point each)
    build_table_kernel<<<65, 256, smem>>>(W1, b1, W2, b2, W3, log_m);
    hnn_kernel<<<(B + SPB - 1) / SPB, BLK>>>(z, out, B);
}

// round 5
// speedup vs baseline: 2.2855x; 1.0845x over previous
#include <cuda_runtime.h>
#include <cuda_bf16.h>
#include <cuda_pipeline.h>
#include <math.h>

#define NPTS   128             // interpolation intervals over s in [0, 10]
#define TAB_N  (NPTS + 4)      // +1 guard point below, +2 above (Catmull-Rom)
#define S_MAX  10.0f           // 1/sqrt(EPS2)
#define EPS2   0.01f
#define BLK    128
#define SPB    128             // samples per tile in hnn_kernel
#define TILES  4               // tiles per block
#define STAGES 3               // cp.async pipeline depth

// g(s) = d(MLP)/ds at s_k = (k-1)*h, k = 0..NPTS+3
__device__ float g_table[TAB_N];
__device__ float minv_g[3];

// ---------------------------------------------------------------------------
// Kernel 1: build the 1-D derivative table. One point per warp.
// Fused forward+backward: tot = sum_k g2_k * (W2 @ u)_k with u_j = W1_j*silu'(a1_j)
// -> W2 traversed ONCE row-major with two accumulators per output row.
// ---------------------------------------------------------------------------
__global__ void build_table_kernel(const float* __restrict__ W1,
                                   const float* __restrict__ b1,
                                   const float* __restrict__ W2,
                                   const float* __restrict__ b2,
                                   const float* __restrict__ W3,
                                   const float* __restrict__ log_m)
{
    extern __shared__ float sm[];
    float* sW2  = sm;                       // [128][129]
    float* sbuf = sm + 128 * 129;           // per-warp: 128 h1 + 128 u

    const float4* W24 = (const float4*)W2;
    for (int idx = threadIdx.x; idx < 128 * 32; idx += blockDim.x) {
        const float4 v = W24[idx];
        float* d = sW2 + (idx >> 5) * 129 + ((idx & 31) << 2);
        d[0] = v.x; d[1] = v.y; d[2] = v.z; d[3] = v.w;
    }
    if (blockIdx.x == 0 && threadIdx.x < 3)
        minv_g[threadIdx.x] = 1.0f / (expf(log_m[threadIdx.x]) + 1e-8f);
    __syncthreads();

    const int warp = threadIdx.x >> 5;
    const int lane = threadIdx.x & 31;
    float* sh1 = sbuf + warp * 256;
    float* su  = sh1 + 128;

    const int nwarps = (blockDim.x >> 5) * gridDim.x;
    const int gw     = blockIdx.x * (blockDim.x >> 5) + warp;
    const float hstep = S_MAX / (float)NPTS;

    for (int pt = gw; pt < TAB_N; pt += nwarps) {
        const float s = (float)(pt - 1) * hstep;

        #pragma unroll
        for (int m = 0; m < 4; m++) {
            const int j = lane + 32 * m;
            const float w  = W1[j];
            const float a  = fmaf(w, s, b1[j]);
            const float sg = 1.0f / (1.0f + __expf(-a));
            sh1[j] = a * sg;
            su[j]  = w * sg * (1.0f + a * (1.0f - sg));
        }
        __syncwarp();

        float acch0 = b2[lane], acch1 = b2[lane + 32],
              acch2 = b2[lane + 64], acch3 = b2[lane + 96];
        float accu0 = 0.f, accu1 = 0.f, accu2 = 0.f, accu3 = 0.f;
        const float* w0 = sW2 + lane * 129;
        #pragma unroll 4
        for (int j = 0; j < 128; j++) {
            const float hj = sh1[j];
            const float uj = su[j];
            const float wa = w0[j];
            const float wb = w0[32 * 129 + j];
            const float wc = w0[64 * 129 + j];
            const float wd = w0[96 * 129 + j];
            acch0 = fmaf(wa, hj, acch0);  accu0 = fmaf(wa, uj, accu0);
            acch1 = fmaf(wb, hj, acch1);  accu1 = fmaf(wb, uj, accu1);
            acch2 = fmaf(wc, hj, acch2);  accu2 = fmaf(wc, uj, accu2);
            acch3 = fmaf(wd, hj, acch3);  accu3 = fmaf(wd, uj, accu3);
        }

        float tot = 0.0f;
        #pragma unroll
        for (int m = 0; m < 4; m++) {
            const float a  = (m == 0) ? acch0 : (m == 1) ? acch1 : (m == 2) ? acch2 : acch3;
            const float au = (m == 0) ? accu0 : (m == 1) ? accu1 : (m == 2) ? accu2 : accu3;
            const float sg = 1.0f / (1.0f + __expf(-a));
            tot = fmaf(W3[lane + 32 * m] * sg * (1.0f + a * (1.0f - sg)), au, tot);
        }
        #pragma unroll
        for (int off = 16; off; off >>= 1)
            tot += __shfl_xor_sync(0xffffffffu, tot, off);
        if (lane == 0) g_table[pt] = tot;
        __syncwarp();
    }
}

// Catmull-Rom lookup of g(s) from a shared-memory table
__device__ __forceinline__ float lookup_g(const float* __restrict__ tab, float s)
{
    const float inv_h = (float)NPTS / S_MAX;
    const float u = s * inv_h;
    int i = (int)u;
    if (i > NPTS - 1) i = NPTS - 1;
    const float t  = u - (float)i;
    const float p0 = tab[i];
    const float p1 = tab[i + 1];
    const float p2 = tab[i + 2];
    const float p3 = tab[i + 3];
    return p1 + 0.5f * t * ((p2 - p0)
           + t * ((2.0f * p0 - 5.0f * p1 + 4.0f * p2 - p3)
           + t * (3.0f * (p1 - p2) + (p3 - p0))));
}

// ---------------------------------------------------------------------------
// Kernel 2: software-pipelined. Each block processes TILES tiles of SPB
// samples; cp.async prefetches tile t+2 while tile t computes, hiding DRAM
// latency inside the block instead of relying on cross-block overlap.
// ---------------------------------------------------------------------------
__global__ void __launch_bounds__(BLK) hnn_kernel(const float* __restrict__ z,
                                                  float* __restrict__ out, int B)
{
    __shared__ __align__(16) float sbuf[STAGES][SPB * 18];  // 27648 B
    __shared__ __align__(16) float s_tab[TAB_N];
    __shared__ float s_minv[3];

    const int tid = threadIdx.x;
    for (int i = tid; i < TAB_N; i += BLK) s_tab[i] = g_table[i];
    if (tid < 3) s_minv[tid] = minv_g[tid];

    const int ntiles_tot = (B + SPB - 1) / SPB;
    const int tile0 = blockIdx.x * TILES;
    const int T = min(TILES, ntiles_tot - tile0);
    if (T <= 0) return;

    // async-load local tile t into its ring buffer
    auto load_tile = [&](int t) {
        const int  tile  = tile0 + t;
        const int  nrows = min(SPB, B - tile * SPB);
        const int  nelem = nrows * 18;
        const float* src = z + (size_t)tile * (SPB * 18);
        float* dst = sbuf[t % STAGES];
        const int n4 = nelem >> 2;
        for (int i = tid; i < n4; i += BLK)
            __pipeline_memcpy_async(dst + 4 * i, src + 4 * i, 16);
        for (int i = (n4 << 2) + tid; i < nelem; i += BLK)
            __pipeline_memcpy_async(dst + i, src + i, 4);
    };

    // prologue: keep STAGES-1 tiles in flight (always commit to keep counts uniform)
    for (int s = 0; s < STAGES - 1; ++s) {
        if (s < T) load_tile(s);
        __pipeline_commit();
    }

    for (int t = 0; t < T; ++t) {
        if (t + STAGES - 1 < T) load_tile(t + STAGES - 1);
        __pipeline_commit();
        __pipeline_wait_prior(STAGES - 1);   // group for tile t complete
        __syncthreads();                     // all threads' copies + s_tab visible

        float* buf = sbuf[t % STAGES];
        const int tile  = tile0 + t;
        const int nrows = min(SPB, B - tile * SPB);

        if (tid < nrows) {
            const float mi0 = s_minv[0], mi1 = s_minv[1], mi2 = s_minv[2];
            float* r = buf + tid * 18;
            float q[9], p[9], f[9];
            #pragma unroll
            for (int c = 0; c < 9; c++) { q[c] = r[c]; p[c] = r[9 + c]; }

            #pragma unroll
            for (int c = 0; c < 3; c++) {
                r[c]     = p[c]     * mi0;      // dq/dt
                r[3 + c] = p[3 + c] * mi1;
                r[6 + c] = p[6 + c] * mi2;
            }
            #pragma unroll
            for (int c = 0; c < 9; c++) f[c] = 0.0f;

            const int PI[3] = {0, 0, 1};
            const int PJ[3] = {1, 2, 2};
            #pragma unroll
            for (int pr = 0; pr < 3; pr++) {
                const int bi = PI[pr] * 3, bj = PJ[pr] * 3;
                const float dx = q[bi]     - q[bj];
                const float dy = q[bi + 1] - q[bj + 1];
                const float dz = q[bi + 2] - q[bj + 2];
                const float r2 = fmaf(dx, dx, fmaf(dy, dy, fmaf(dz, dz, EPS2)));
                const float s  = rsqrtf(r2);            // 1/d
                const float g  = lookup_g(s_tab, s);    // dV_pair/ds
                const float w  = g * s * s * s;         // g / d^3
                f[bi]     += w * dx;  f[bi + 1] += w * dy;  f[bi + 2] += w * dz;
                f[bj]     -= w * dx;  f[bj + 1] -= w * dy;  f[bj + 2] -= w * dz;
            }
            #pragma unroll
            for (int c = 0; c < 9; c++) r[9 + c] = f[c];   // dp/dt
        }
        __syncthreads();

        // coalesced store
        const int nelem = nrows * 18;
        const int n4 = nelem >> 2;
        float* dstg = out + (size_t)tile * (SPB * 18);
        float4* o4 = (float4*)dstg;
        const float4* s4 = (const float4*)buf;
        for (int i = tid; i < n4; i += BLK) o4[i] = s4[i];
        for (int i = (n4 << 2) + tid; i < nelem; i += BLK) dstg[i] = buf[i];
        __syncthreads();   // buffer safe to overwrite by next prefetch
    }
}

extern "C" void kernel_launch(void* const* d_in, const int* in_sizes, int n_in,
                              void* d_out, int out_size)
{
    const float* z     = (const float*)d_in[0];
    const float* log_m = (const float*)d_in[1];
    const float* W1    = (const float*)d_in[2];
    const float* b1    = (const float*)d_in[3];
    const float* W2    = (const float*)d_in[4];
    const float* b2    = (const float*)d_in[5];
    const float* W3    = (const float*)d_in[6];
    // d_in[7] = b3 drops out of the gradient
    float* out = (float*)d_out;
    const int B = in_sizes[0] / 18;

    const size_t smem = (128 * 129 + 8 * 256) * sizeof(float);  // 74240 B
    cudaFuncSetAttribute(build_table_kernel,
                         cudaFuncAttributeMaxDynamicSharedMemorySize, (int)smem);

    // 17 blocks x 8 warps = 136 warps >= 132 table points (one point each)
    build_table_kernel<<<17, 256, smem>>>(W1, b1, W2, b2, W3, log_m);

    const int ntiles = (B + SPB - 1) / SPB;
    const int grid   = (ntiles + TILES - 1) / TILES;   // 512 for B=262144
    hnn_kernel<<<grid, BLK>>>(z, out, B);
}